// round 8
// baseline (speedup 1.0000x reference)
#include <cuda_runtime.h>

// Problem constants
#define Hdim 512
#define Bdim 256
#define Tdim 1024
#define NCLS 10

// Geometry: 16 clusters (one per 16-batch-column group) x 8 CTAs (row-groups).
// All h traffic stays inside a cluster -> no grid-wide sync needed.
#define NCTA 128
#define TPB  128
#define CLUS 8         // CTAs per cluster (row-groups)
#define HR 64          // rows of h computed per CTA
#define BC 16          // batch columns per cluster/CTA
#define PW 514         // smem pitch (floats) for W slice  (conflict-free)
#define PH 516         // smem pitch (floats) for hT block (conflict-free, 16B-aligned rows)
#define SMEM_BYTES ((HR * PW + BC * PH) * 4)   // 164,608 B

// Persistent state: double-buffered hidden state, TRANSPOSED: hT[b][k].
__device__ float g_hT[2][Bdim * Hdim];

// Packed fp32x2 FMA (Blackwell): 2 FMA per instruction on the fma pipe.
__device__ __forceinline__ void fma2(unsigned long long& acc,
                                     unsigned long long a,
                                     unsigned long long b) {
    asm("fma.rn.f32x2 %0, %1, %2, %0;" : "+l"(acc) : "l"(a), "l"(b));
}

__device__ __forceinline__ void cluster_sync() {
    // arrive has release semantics, wait has acquire -> orders the __stcg
    // h stores against the peers' __ldcg reads. Also acts as a full CTA barrier.
    asm volatile("barrier.cluster.arrive.aligned;" ::: "memory");
    asm volatile("barrier.cluster.wait.aligned;" ::: "memory");
}

__global__ void __launch_bounds__(TPB, 1) __cluster_dims__(CLUS, 1, 1)
rnn_persistent(const float* __restrict__ x,       // [B, T]
               const float* __restrict__ h_init,  // [H]
               const float* __restrict__ W_hx,    // [H]
               const float* __restrict__ W_hh,    // [H, H]
               const float* __restrict__ b_h,     // [H]
               const float* __restrict__ W_ph,    // [NCLS, H]
               const float* __restrict__ b_p,     // [NCLS]
               float* __restrict__ out)           // [B, NCLS]
{
    extern __shared__ float smem[];
    float* sW = smem;                 // [HR][PW]  W_hh row-slice
    float* sH = smem + HR * PW;       // [BC][PH]  hT block: sH[c][k]

    const int cta  = blockIdx.x;
    const int tid  = threadIdx.x;
    const int rank = cta & (CLUS - 1);   // row-group within cluster
    const int cg   = cta >> 3;           // cluster id = column-group
    const int rBase = rank * HR;
    const int cBase = cg * BC;

    // ---- One-time: load W_hh slice (rows rBase..rBase+HR) into smem ----
    for (int i = tid; i < HR * (Hdim / 4); i += TPB) {
        int r  = i >> 7;          // Hdim/4 == 128
        int k4 = i & 127;
        float4 v = reinterpret_cast<const float4*>(W_hh + (rBase + r) * Hdim)[k4];
        float* d = sW + r * PW + (k4 << 2);
        d[0] = v.x; d[1] = v.y; d[2] = v.z; d[3] = v.w;
    }

    // ---- One-time: init hT buffer 0 with broadcast h_init.
    // CTA cta writes global elements [cta*1024, (cta+1)*1024) == exactly the
    // batch rows owned by its own cluster -> first cluster_sync covers visibility.
    {
        const int per  = (Bdim * Hdim) / NCTA;   // 1024
        const int base = cta * per;
        for (int i = tid; i < per; i += TPB) {
            int e = base + i;
            __stcg(&g_hT[0][e], h_init[e & (Hdim - 1)]);
        }
    }

    // ---- Per-thread tile: 4 rows x 2 cols, f32x2-paired over k ----
    const int lane = tid & 31;
    const int wrp  = tid >> 5;
    const int trg  = wrp * 4 + (lane >> 3);   // thread-row group 0..15
    const int tc   = lane & 7;                // thread-col 0..7
    const int r0   = trg * 4;                 // local rows r0..r0+3
    const int c0   = tc * 2;                  // local cols c0, c0+1

    float whx[4], bh[4];
#pragma unroll
    for (int i = 0; i < 4; i++) {
        whx[i] = W_hx[rBase + r0 + i];
        bh[i]  = b_h[rBase + r0 + i];
    }
    const float* xr0 = x + (cBase + c0) * Tdim;
    const float* xr1 = xr0 + Tdim;

    const unsigned long long* wp0 = reinterpret_cast<const unsigned long long*>(sW + (r0 + 0) * PW);
    const unsigned long long* wp1 = reinterpret_cast<const unsigned long long*>(sW + (r0 + 1) * PW);
    const unsigned long long* wp2 = reinterpret_cast<const unsigned long long*>(sW + (r0 + 2) * PW);
    const unsigned long long* wp3 = reinterpret_cast<const unsigned long long*>(sW + (r0 + 3) * PW);
    const unsigned long long* hp0 = reinterpret_cast<const unsigned long long*>(sH + (c0 + 0) * PH);
    const unsigned long long* hp1 = reinterpret_cast<const unsigned long long*>(sH + (c0 + 1) * PH);

    cluster_sync();   // W slice + h0 init visible inside the cluster

    for (int t = 0; t < Tdim; t++) {
        const float* hc = g_hT[t & 1];
        float*       hn = g_hT[(t + 1) & 1];

        // Prefetch this step's x early (overlaps load + compute).
        const float xv0 = __ldcg(xr0 + t);
        const float xv1 = __ldcg(xr1 + t);

        // Load the cluster's hT block: 16 rows x 512 floats, fully coalesced
        // LDG.128 + conflict-free STS.128 (one 2KB row per 128-thread sweep).
        for (int i = tid; i < BC * (Hdim / 4); i += TPB) {
            int cc = i >> 7;          // Hdim/4 == 128
            int k4 = i & 127;
            float4 v = __ldcg(reinterpret_cast<const float4*>(hc + (cBase + cc) * Hdim) + k4);
            *reinterpret_cast<float4*>(sH + cc * PH + (k4 << 2)) = v;
        }
        __syncthreads();

        unsigned long long acc00 = 0ull, acc01 = 0ull;
        unsigned long long acc10 = 0ull, acc11 = 0ull;
        unsigned long long acc20 = 0ull, acc21 = 0ull;
        unsigned long long acc30 = 0ull, acc31 = 0ull;

#pragma unroll 8
        for (int k2 = 0; k2 < Hdim / 2; k2++) {
            unsigned long long hv0 = hp0[k2];
            unsigned long long hv1 = hp1[k2];
            unsigned long long w0  = wp0[k2];
            unsigned long long w1  = wp1[k2];
            unsigned long long w2  = wp2[k2];
            unsigned long long w3  = wp3[k2];
            fma2(acc00, w0, hv0);  fma2(acc01, w0, hv1);
            fma2(acc10, w1, hv0);  fma2(acc11, w1, hv1);
            fma2(acc20, w2, hv0);  fma2(acc21, w2, hv1);
            fma2(acc30, w3, hv0);  fma2(acc31, w3, hv1);
        }

        // Epilogue: reduce pairs, add input/bias, tanh, store transposed:
        // one STG.128 per column (4 consecutive rows).
        {
            unsigned long long aAarr[4] = {acc00, acc10, acc20, acc30};
            unsigned long long aBarr[4] = {acc01, acc11, acc21, acc31};
            float4 oA, oB;
            float* pA = &oA.x;
            float* pB = &oB.x;
#pragma unroll
            for (int i = 0; i < 4; i++) {
                float2 aA = *reinterpret_cast<float2*>(&aAarr[i]);
                float2 aB = *reinterpret_cast<float2*>(&aBarr[i]);
                pA[i] = tanhf((aA.x + aA.y) + whx[i] * xv0 + bh[i]);
                pB[i] = tanhf((aB.x + aB.y) + whx[i] * xv1 + bh[i]);
            }
            float* dA = hn + (cBase + c0 + 0) * Hdim + rBase + r0;
            float* dB = hn + (cBase + c0 + 1) * Hdim + rBase + r0;
            __stcg(reinterpret_cast<float4*>(dA), oA);
            __stcg(reinterpret_cast<float4*>(dB), oB);
        }

        cluster_sync();   // release h stores to cluster peers; guards sH reuse
    }

    // ---- Final projection (cluster-local batch columns only).
    // T even -> h_last lives in g_hT[0], layout [B][H] (contiguous dot!).
    // Each cluster owns 16 b's -> 160 outputs; 20 per CTA.
    if (tid < 20) {
        const int o  = rank * 20 + tid;          // 0..159 within cluster
        const int b  = cBase + o / NCLS;
        const int n  = o % NCLS;
        const float* wr = W_ph + n * Hdim;
        const float* hf = g_hT[0] + b * Hdim;
        float s = b_p[n];
#pragma unroll 4
        for (int k4 = 0; k4 < Hdim / 4; k4++) {
            float4 w = reinterpret_cast<const float4*>(wr)[k4];
            float4 h = __ldcg(reinterpret_cast<const float4*>(hf) + k4);
            s += w.x * h.x + w.y * h.y + w.z * h.z + w.w * h.w;
        }
        out[b * NCLS + n] = s;
    }
}

extern "C" void kernel_launch(void* const* d_in, const int* in_sizes, int n_in,
                              void* d_out, int out_size) {
    const float* x      = (const float*)d_in[0];
    const float* h_init = (const float*)d_in[1];
    const float* W_hx   = (const float*)d_in[2];
    const float* W_hh   = (const float*)d_in[3];
    const float* b_h    = (const float*)d_in[4];
    const float* W_ph   = (const float*)d_in[5];
    const float* b_p    = (const float*)d_in[6];
    float* out = (float*)d_out;

    cudaFuncSetAttribute(rnn_persistent,
                         cudaFuncAttributeMaxDynamicSharedMemorySize, SMEM_BYTES);

    rnn_persistent<<<NCTA, TPB, SMEM_BYTES, 0>>>(x, h_init, W_hx, W_hh,
                                                 b_h, W_ph, b_p, out);
}

// round 11
// speedup vs baseline: 1.8435x; 1.8435x over previous
#include <cuda_runtime.h>

// Problem constants
#define Hdim 512
#define Bdim 256
#define Tdim 1024
#define NCLS 10

// Geometry: 128 CTAs = 8 row-groups x 16 col-groups, 256 threads each.
// All h traffic is column-group-local -> 16 independent 8-way barriers.
#define NCTA 128
#define TPB  256
#define NCG  16        // column groups
#define NRG  8         // row groups (CTAs per barrier group)
#define HR 64          // rows of h computed per CTA
#define BC 16          // batch columns per CTA
#define PW 514         // smem pitch (floats) for W slice  (conflict-free)
#define PH 514         // smem pitch (floats) for hT block (conflict-free LDS)
#define SMEM_BYTES ((HR * PW + BC * PH) * 4)   // 164,480 B

// Persistent state: double-buffered hidden state, TRANSPOSED: hT[b][k].
__device__ float g_hT[2][Bdim * Hdim];
// One barrier counter per column group, padded to 128B lines.
__device__ unsigned int g_bar[NCG * 32];

// Packed fp32x2 FMA (Blackwell): 2 FMA per instruction on the fma pipe.
__device__ __forceinline__ void fma2(unsigned long long& acc,
                                     unsigned long long a,
                                     unsigned long long b) {
    asm("fma.rn.f32x2 %0, %1, %2, %0;" : "+l"(acc) : "l"(a), "l"(b));
}

__global__ void __launch_bounds__(TPB, 1)
rnn_persistent(const float* __restrict__ x,       // [B, T]
               const float* __restrict__ h_init,  // [H]
               const float* __restrict__ W_hx,    // [H]
               const float* __restrict__ W_hh,    // [H, H]
               const float* __restrict__ b_h,     // [H]
               const float* __restrict__ W_ph,    // [NCLS, H]
               const float* __restrict__ b_p,     // [NCLS]
               float* __restrict__ out)           // [B, NCLS]
{
    extern __shared__ float smem[];
    float* sW = smem;                 // [HR][PW]  W_hh row-slice
    float* sH = smem + HR * PW;       // [BC][PH]  hT block: sH[c][k]

    const int cta = blockIdx.x;
    const int tid = threadIdx.x;
    const int cg  = cta & (NCG - 1);     // column group -> barrier group
    const int rg  = cta >> 4;            // row group
    const int rBase = rg * HR;
    const int cBase = cg * BC;

    volatile unsigned int* barp = &g_bar[cg * 32];

    // ---- One-time: load W_hh slice (rows rBase..rBase+HR) into smem ----
    for (int i = tid; i < HR * (Hdim / 4); i += TPB) {
        int r  = i >> 7;          // Hdim/4 == 128
        int k4 = i & 127;
        float4 v = reinterpret_cast<const float4*>(W_hh + (rBase + r) * Hdim)[k4];
        float* d = sW + r * PW + (k4 << 2);   // scalar stores: pitch not 16B-aligned
        d[0] = v.x; d[1] = v.y; d[2] = v.z; d[3] = v.w;
    }

    // ---- One-time: init hT buffer 0 with broadcast h_init.
    // CTA cta writes batch rows [cta*2, cta*2+2) -> b/16 == cg: group-local.
    {
        const int per  = (Bdim * Hdim) / NCTA;   // 1024
        const int base = cta * per;
        for (int i = tid; i < per; i += TPB) {
            int e = base + i;
            __stcg(&g_hT[0][e], h_init[e & (Hdim - 1)]);
        }
    }

    // ---- Per-thread tile: 2 rows x 2 cols, f32x2-paired over k ----
    // 8 warps; warp-local: 4 row-subgroups x 8 col-subgroups.
    const int lane = tid & 31;
    const int wrp  = tid >> 5;
    const int trg  = wrp * 4 + (lane >> 3);   // thread-row group 0..31
    const int tc   = lane & 7;                // thread-col 0..7
    const int r0   = trg * 2;                 // local rows r0, r0+1 (even)
    const int c0   = tc * 2;                  // local cols c0, c0+1 (even)

    const float whx0 = W_hx[rBase + r0];
    const float whx1 = W_hx[rBase + r0 + 1];
    const float bh0  = b_h[rBase + r0];
    const float bh1  = b_h[rBase + r0 + 1];
    const float* xr0 = x + (cBase + c0) * Tdim;
    const float* xr1 = xr0 + Tdim;

    // r0, c0 even -> float offsets even -> 8B-aligned u64 pointers. OK.
    const unsigned long long* wp0 = reinterpret_cast<const unsigned long long*>(sW + (r0 + 0) * PW);
    const unsigned long long* wp1 = reinterpret_cast<const unsigned long long*>(sW + (r0 + 1) * PW);
    const unsigned long long* hp0 = reinterpret_cast<const unsigned long long*>(sH + (c0 + 0) * PH);
    const unsigned long long* hp1 = reinterpret_cast<const unsigned long long*>(sH + (c0 + 1) * PH);

    unsigned int target = NRG;

    // Column-group barrier: 8 arrivals on a private counter.
#define GROUP_SYNC()                                                  \
    do {                                                              \
        __threadfence();                                              \
        __syncthreads();                                              \
        if (tid == 0) {                                               \
            atomicAdd((unsigned int*)barp, 1u);                       \
            while (*barp < target) { }                                \
            __threadfence();                                          \
        }                                                             \
        __syncthreads();                                              \
        target += NRG;                                                \
    } while (0)

    GROUP_SYNC();   // W slice + h0 init visible inside the group

    for (int t = 0; t < Tdim; t++) {
        const float* hc = g_hT[t & 1];
        float*       hn = g_hT[(t + 1) & 1];

        // Prefetch this step's x early.
        const float xv0 = __ldcg(xr0 + t);
        const float xv1 = __ldcg(xr1 + t);

        // Load the group's hT block: 16 rows x 512 floats, coalesced LDG.128.
        // STS as 2x float2 (sH row pitch 514 floats is 8B- but not 16B-aligned).
        for (int i = tid; i < BC * (Hdim / 4); i += TPB) {
            int cc = i >> 7;          // Hdim/4 == 128
            int k4 = i & 127;
            float4 v = __ldcg(reinterpret_cast<const float4*>(hc + (cBase + cc) * Hdim) + k4);
            float* d = sH + cc * PH + (k4 << 2);
            *reinterpret_cast<float2*>(d + 0) = make_float2(v.x, v.y);
            *reinterpret_cast<float2*>(d + 2) = make_float2(v.z, v.w);
        }
        __syncthreads();

        unsigned long long acc00 = 0ull, acc01 = 0ull;
        unsigned long long acc10 = 0ull, acc11 = 0ull;

#pragma unroll 16
        for (int k2 = 0; k2 < Hdim / 2; k2++) {
            unsigned long long hv0 = hp0[k2];
            unsigned long long hv1 = hp1[k2];
            unsigned long long w0  = wp0[k2];
            unsigned long long w1  = wp1[k2];
            fma2(acc00, w0, hv0);  fma2(acc01, w0, hv1);
            fma2(acc10, w1, hv0);  fma2(acc11, w1, hv1);
        }

        // Epilogue: reduce pairs, add input/bias, tanh, store transposed:
        // one float2 STG per column (2 consecutive k-rows, 8B-aligned).
        {
            float2 a00 = *reinterpret_cast<float2*>(&acc00);
            float2 a01 = *reinterpret_cast<float2*>(&acc01);
            float2 a10 = *reinterpret_cast<float2*>(&acc10);
            float2 a11 = *reinterpret_cast<float2*>(&acc11);
            float2 oA, oB;
            oA.x = tanhf((a00.x + a00.y) + whx0 * xv0 + bh0);
            oA.y = tanhf((a10.x + a10.y) + whx1 * xv0 + bh1);
            oB.x = tanhf((a01.x + a01.y) + whx0 * xv1 + bh0);
            oB.y = tanhf((a11.x + a11.y) + whx1 * xv1 + bh1);
            float* dA = hn + (cBase + c0 + 0) * Hdim + rBase + r0;
            float* dB = hn + (cBase + c0 + 1) * Hdim + rBase + r0;
            __stcg(reinterpret_cast<float2*>(dA), oA);
            __stcg(reinterpret_cast<float2*>(dB), oB);
        }

        GROUP_SYNC();   // release h stores to group peers; guards sH reuse
    }

    // ---- Final projection (group-local batch columns).
    // T even -> h_last lives in g_hT[0], layout [B][H] (contiguous dot).
    // Each group owns 16 b's -> 160 outputs; 20 per CTA.
    if (tid < 20) {
        const int o  = rg * 20 + tid;            // 0..159 within group
        const int b  = cBase + o / NCLS;
        const int n  = o % NCLS;
        const float* wr = W_ph + n * Hdim;
        const float* hf = g_hT[0] + b * Hdim;
        float s = b_p[n];
#pragma unroll 4
        for (int k4 = 0; k4 < Hdim / 4; k4++) {
            float4 w = reinterpret_cast<const float4*>(wr)[k4];
            float4 h = __ldcg(reinterpret_cast<const float4*>(hf) + k4);
            s += w.x * h.x + w.y * h.y + w.z * h.z + w.w * h.w;
        }
        out[b * NCLS + n] = s;
    }
#undef GROUP_SYNC
}

extern "C" void kernel_launch(void* const* d_in, const int* in_sizes, int n_in,
                              void* d_out, int out_size) {
    const float* x      = (const float*)d_in[0];
    const float* h_init = (const float*)d_in[1];
    const float* W_hx   = (const float*)d_in[2];
    const float* W_hh   = (const float*)d_in[3];
    const float* b_h    = (const float*)d_in[4];
    const float* W_ph   = (const float*)d_in[5];
    const float* b_p    = (const float*)d_in[6];
    float* out = (float*)d_out;

    cudaFuncSetAttribute(rnn_persistent,
                         cudaFuncAttributeMaxDynamicSharedMemorySize, SMEM_BYTES);

    // Reset the barrier counters every launch (graph-capturable, no allocs).
    void* barp = nullptr;
    cudaGetSymbolAddress(&barp, g_bar);
    cudaMemsetAsync(barp, 0, NCG * 32 * sizeof(unsigned int), 0);

    rnn_persistent<<<NCTA, TPB, SMEM_BYTES, 0>>>(x, h_init, W_hx, W_hh,
                                                 b_h, W_ph, b_p, out);
}

// round 12
// speedup vs baseline: 1.8621x; 1.0101x over previous
#include <cuda_runtime.h>

// Problem constants
#define Hdim 512
#define Bdim 256
#define Tdim 1024
#define NCLS 10

// Geometry: 128 CTAs = 8 row-groups x 16 col-groups, 256 threads each.
// All h traffic is column-group-local -> 16 independent 8-way barriers.
#define NCTA 128
#define TPB  256
#define NCG  16        // column groups
#define NRG  8         // row groups (CTAs per barrier group)
#define HR 64          // rows of h computed per CTA
#define BC 16          // batch columns per CTA
#define PW 516         // smem pitch (floats): 16B-aligned rows, conflict-free (derived)
#define PH 516
#define SMEM_BYTES ((HR * PW + BC * PH) * 4)   // 165,120 B

// Persistent state: double-buffered hidden state, TRANSPOSED: hT[b][k].
__device__ float g_hT[2][Bdim * Hdim];
// One barrier counter per column group, padded to 128B lines.
__device__ unsigned int g_bar[NCG * 32];

// Packed fp32x2 FMA (Blackwell): 2 FMA per instruction on the fma pipe.
__device__ __forceinline__ void fma2(unsigned long long& acc,
                                     unsigned long long a,
                                     unsigned long long b) {
    asm("fma.rn.f32x2 %0, %1, %2, %0;" : "+l"(acc) : "l"(a), "l"(b));
}

__global__ void __launch_bounds__(TPB, 1)
rnn_persistent(const float* __restrict__ x,       // [B, T]
               const float* __restrict__ h_init,  // [H]
               const float* __restrict__ W_hx,    // [H]
               const float* __restrict__ W_hh,    // [H, H]
               const float* __restrict__ b_h,     // [H]
               const float* __restrict__ W_ph,    // [NCLS, H]
               const float* __restrict__ b_p,     // [NCLS]
               float* __restrict__ out)           // [B, NCLS]
{
    extern __shared__ float smem[];
    float* sW = smem;                 // [HR][PW]  W_hh row-slice
    float* sH = smem + HR * PW;       // [BC][PH]  hT block: sH[c][k]

    const int cta = blockIdx.x;
    const int tid = threadIdx.x;
    const int cg  = cta & (NCG - 1);     // column group -> barrier group
    const int rg  = cta >> 4;            // row group
    const int rBase = rg * HR;
    const int cBase = cg * BC;

    volatile unsigned int* barp = &g_bar[cg * 32];

    // ---- One-time: load W_hh slice (rows rBase..rBase+HR) into smem ----
    // Pitch 516 floats = 2064 B: 16B-aligned -> STS.128 OK.
    for (int i = tid; i < HR * (Hdim / 4); i += TPB) {
        int r  = i >> 7;          // Hdim/4 == 128
        int k4 = i & 127;
        float4 v = reinterpret_cast<const float4*>(W_hh + (rBase + r) * Hdim)[k4];
        *reinterpret_cast<float4*>(sW + r * PW + (k4 << 2)) = v;
    }

    // ---- One-time: init hT buffer 0 with broadcast h_init.
    // GROUP-LOCAL: CTA (rg,cg) inits batch rows cBase+2*rg, cBase+2*rg+1,
    // so the group's own barrier orders these writes before step-0 reads.
    {
        float* dst = &g_hT[0][(cBase + 2 * rg) * Hdim];
        for (int i = tid; i < 2 * Hdim; i += TPB)
            __stcg(&dst[i], h_init[i & (Hdim - 1)]);
    }

    // ---- Per-thread tile: rows {2*trg, 2*trg+1} x cols {tc, tc+8} ----
    // 8 warps; warp-local: 4 row-subgroups x 8 col-subgroups.
    const int lane = tid & 31;
    const int wrp  = tid >> 5;
    const int trg  = wrp * 4 + (lane >> 3);   // thread-row group 0..31
    const int tc   = lane & 7;                // thread-col 0..7
    const int r0   = trg * 2;                 // local rows r0, r0+1 (even)
    const int cA   = tc;                      // local col A
    const int cB   = tc + 8;                  // local col B

    const float whx0 = W_hx[rBase + r0];
    const float whx1 = W_hx[rBase + r0 + 1];
    const float bh0  = b_h[rBase + r0];
    const float bh1  = b_h[rBase + r0 + 1];
    const float* xrA = x + (cBase + cA) * Tdim;
    const float* xrB = x + (cBase + cB) * Tdim;

    // 16B-aligned row bases (pitch 2064 B).
    const longlong2* wp0 = reinterpret_cast<const longlong2*>(sW + (r0 + 0) * PW);
    const longlong2* wp1 = reinterpret_cast<const longlong2*>(sW + (r0 + 1) * PW);
    const longlong2* hpA = reinterpret_cast<const longlong2*>(sH + cA * PH);
    const longlong2* hpB = reinterpret_cast<const longlong2*>(sH + cB * PH);

    unsigned int target = NRG;

    // Column-group barrier: 8 arrivals on a private counter.
#define GROUP_SYNC()                                                  \
    do {                                                              \
        __threadfence();                                              \
        __syncthreads();                                              \
        if (tid == 0) {                                               \
            atomicAdd((unsigned int*)barp, 1u);                       \
            while (*barp < target) { }                                \
            __threadfence();                                          \
        }                                                             \
        __syncthreads();                                              \
        target += NRG;                                                \
    } while (0)

    GROUP_SYNC();   // W slice + h0 init visible inside the group

    for (int t = 0; t < Tdim; t++) {
        const float* hc = g_hT[t & 1];
        float*       hn = g_hT[(t + 1) & 1];

        // Prefetch this step's x early.
        const float xvA = __ldcg(xrA + t);
        const float xvB = __ldcg(xrB + t);

        // Load the group's hT block: 16 rows x 512 floats, coalesced LDG.128
        // + aligned STS.128 (pitch 2064 B).
        for (int i = tid; i < BC * (Hdim / 4); i += TPB) {
            int cc = i >> 7;          // Hdim/4 == 128
            int k4 = i & 127;
            float4 v = __ldcg(reinterpret_cast<const float4*>(hc + (cBase + cc) * Hdim) + k4);
            *reinterpret_cast<float4*>(sH + cc * PH + (k4 << 2)) = v;
        }
        __syncthreads();

        unsigned long long acc00 = 0ull, acc01 = 0ull;
        unsigned long long acc10 = 0ull, acc11 = 0ull;

        // Macro-iter = 4 k: 4x LDS.128 + 8x FFMA2.
#pragma unroll 8
        for (int k4 = 0; k4 < Hdim / 4; k4++) {
            longlong2 w0 = wp0[k4];
            longlong2 w1 = wp1[k4];
            longlong2 hA = hpA[k4];
            longlong2 hB = hpB[k4];
            fma2(acc00, (unsigned long long)w0.x, (unsigned long long)hA.x);
            fma2(acc01, (unsigned long long)w0.x, (unsigned long long)hB.x);
            fma2(acc10, (unsigned long long)w1.x, (unsigned long long)hA.x);
            fma2(acc11, (unsigned long long)w1.x, (unsigned long long)hB.x);
            fma2(acc00, (unsigned long long)w0.y, (unsigned long long)hA.y);
            fma2(acc01, (unsigned long long)w0.y, (unsigned long long)hB.y);
            fma2(acc10, (unsigned long long)w1.y, (unsigned long long)hA.y);
            fma2(acc11, (unsigned long long)w1.y, (unsigned long long)hB.y);
        }

        // Epilogue: reduce pairs, add input/bias, tanh, store transposed:
        // per column one float2 STG (rows r0, r0+1 contiguous in hT[b][k]).
        {
            float2 a00 = *reinterpret_cast<float2*>(&acc00);
            float2 a01 = *reinterpret_cast<float2*>(&acc01);
            float2 a10 = *reinterpret_cast<float2*>(&acc10);
            float2 a11 = *reinterpret_cast<float2*>(&acc11);
            float2 oA, oB;
            oA.x = tanhf((a00.x + a00.y) + whx0 * xvA + bh0);
            oA.y = tanhf((a10.x + a10.y) + whx1 * xvA + bh1);
            oB.x = tanhf((a01.x + a01.y) + whx0 * xvB + bh0);
            oB.y = tanhf((a11.x + a11.y) + whx1 * xvB + bh1);
            float* dA = hn + (cBase + cA) * Hdim + rBase + r0;
            float* dB = hn + (cBase + cB) * Hdim + rBase + r0;
            __stcg(reinterpret_cast<float2*>(dA), oA);
            __stcg(reinterpret_cast<float2*>(dB), oB);
        }

        GROUP_SYNC();   // release h stores to group peers; guards sH reuse
    }

    // ---- Final projection (group-local batch columns).
    // T even -> h_last lives in g_hT[0], layout [B][H] (contiguous dot).
    // Each group owns 16 b's -> 160 outputs; 20 per CTA.
    if (tid < 20) {
        const int o  = rg * 20 + tid;            // 0..159 within group
        const int b  = cBase + o / NCLS;
        const int n  = o % NCLS;
        const float* wr = W_ph + n * Hdim;
        const float* hf = g_hT[0] + b * Hdim;
        float s = b_p[n];
#pragma unroll 4
        for (int k4 = 0; k4 < Hdim / 4; k4++) {
            float4 w = reinterpret_cast<const float4*>(wr)[k4];
            float4 h = __ldcg(reinterpret_cast<const float4*>(hf) + k4);
            s += w.x * h.x + w.y * h.y + w.z * h.z + w.w * h.w;
        }
        out[b * NCLS + n] = s;
    }
#undef GROUP_SYNC
}

extern "C" void kernel_launch(void* const* d_in, const int* in_sizes, int n_in,
                              void* d_out, int out_size) {
    const float* x      = (const float*)d_in[0];
    const float* h_init = (const float*)d_in[1];
    const float* W_hx   = (const float*)d_in[2];
    const float* W_hh   = (const float*)d_in[3];
    const float* b_h    = (const float*)d_in[4];
    const float* W_ph   = (const float*)d_in[5];
    const float* b_p    = (const float*)d_in[6];
    float* out = (float*)d_out;

    cudaFuncSetAttribute(rnn_persistent,
                         cudaFuncAttributeMaxDynamicSharedMemorySize, SMEM_BYTES);

    // Reset the barrier counters every launch (graph-capturable, no allocs).
    void* barp = nullptr;
    cudaGetSymbolAddress(&barp, g_bar);
    cudaMemsetAsync(barp, 0, NCG * 32 * sizeof(unsigned int), 0);

    rnn_persistent<<<NCTA, TPB, SMEM_BYTES, 0>>>(x, h_init, W_hx, W_hh,
                                                 b_h, W_ph, b_p, out);
}

// round 13
// speedup vs baseline: 2.6844x; 1.4416x over previous
#include <cuda_runtime.h>

// Problem constants
#define Hdim 512
#define Bdim 256
#define Tdim 1024
#define NCLS 10

// Geometry: 128 CTAs = 8 row-groups x 16 col-groups, 256 threads each.
// All h traffic is column-group-local -> 16 independent 8-way barriers.
// NEW: warps are K-SPLIT — each warp computes the full 64x16 output tile
// for a 64-wide k-slice; partials reduced through a smem slab. This cuts
// smem crossbar traffic ~4x (h block read once per CTA, not once per warp).
#define NCTA 128
#define TPB  256
#define NCG  16        // column groups
#define NRG  8         // row groups (CTAs per barrier group)
#define HR 64          // rows of h computed per CTA
#define BC 16          // batch columns per CTA
#define PW 516         // smem pitch (floats): 16B-aligned rows
#define PH 516
#define SLAB_PITCH 33              // conflict-free scalar slab
#define SLAB_WSTRIDE (32 * SLAB_PITCH)   // 1056 floats per warp
#define SMEM_FLOATS (HR * PW + BC * PH + 8 * SLAB_WSTRIDE + 16)
#define SMEM_BYTES (SMEM_FLOATS * 4)     // 198,976 B

// Persistent state: double-buffered hidden state, TRANSPOSED: hT[b][k].
__device__ float g_hT[2][Bdim * Hdim];
// One barrier counter per column group, padded to 128B lines.
__device__ unsigned int g_bar[NCG * 32];

// Packed fp32x2 FMA (Blackwell): 2 FMA per instruction on the fma pipe.
__device__ __forceinline__ void fma2(unsigned long long& acc,
                                     unsigned long long a,
                                     unsigned long long b) {
    asm("fma.rn.f32x2 %0, %1, %2, %0;" : "+l"(acc) : "l"(a), "l"(b));
}

__global__ void __launch_bounds__(TPB, 1)
rnn_persistent(const float* __restrict__ x,       // [B, T]
               const float* __restrict__ h_init,  // [H]
               const float* __restrict__ W_hx,    // [H]
               const float* __restrict__ W_hh,    // [H, H]
               const float* __restrict__ b_h,     // [H]
               const float* __restrict__ W_ph,    // [NCLS, H]
               const float* __restrict__ b_p,     // [NCLS]
               float* __restrict__ out)           // [B, NCLS]
{
    extern __shared__ float smem[];
    float* sW = smem;                 // [HR][PW]  W_hh row-slice
    float* sH = smem + HR * PW;       // [BC][PH]  hT block: sH[c][k]
    float* sP = sH + BC * PH;         // [8][32][33] partial slab
    float* sX = sP + 8 * SLAB_WSTRIDE;// [16] x values for this step

    const int cta = blockIdx.x;
    const int tid = threadIdx.x;
    const int cg  = cta & (NCG - 1);     // column group -> barrier group
    const int rg  = cta >> 4;            // row group
    const int rBase = rg * HR;
    const int cBase = cg * BC;

    volatile unsigned int* barp = &g_bar[cg * 32];

    // ---- One-time: load W_hh slice (rows rBase..rBase+HR) into smem ----
    for (int i = tid; i < HR * (Hdim / 4); i += TPB) {
        int r  = i >> 7;          // Hdim/4 == 128
        int k4 = i & 127;
        float4 v = reinterpret_cast<const float4*>(W_hh + (rBase + r) * Hdim)[k4];
        *reinterpret_cast<float4*>(sW + r * PW + (k4 << 2)) = v;
    }

    // ---- One-time: init hT buffer 0 with broadcast h_init (GROUP-LOCAL) ----
    {
        float* dst = &g_hT[0][(cBase + 2 * rg) * Hdim];
        for (int i = tid; i < 2 * Hdim; i += TPB)
            __stcg(&dst[i], h_init[i & (Hdim - 1)]);
    }

    // ---- Warp/lane mapping (k-split) ----
    const int lane = tid & 31;
    const int wrp  = tid >> 5;           // warp = k-slice [wrp*64, wrp*64+64)
    const int lr   = lane >> 2;          // 0..7: rows lr + 8*i (i=0..7)
    const int lc   = lane & 3;           // 0..3: cols lc + 4*j (j=0..3)
    const int wk   = wrp * 64;           // k base for this warp

    const float* wbase = sW + lr * PW + wk;
    const float* hbase = sH + lc * PH + wk;
    float* myslab = sP + wrp * SLAB_WSTRIDE + lane * SLAB_PITCH;

    // ---- Reduction-thread mapping: thread tid owns outputs (r, 4*cq+m) ----
    const int rr  = tid >> 2;            // 0..63
    const int cq  = tid & 3;             // col quarter
    const float whx_r = W_hx[rBase + rr];
    const float bh_r  = b_h[rBase + rr];
    const int   slot  = (rr >> 3) * 4 + cq;       // fixed slab slot
    const float* rdslab = sP + ((rr & 7) * 4) * SLAB_PITCH + slot;

    unsigned int target = NRG;

    // Column-group barrier: 8 arrivals on a private counter.
#define GROUP_SYNC()                                                  \
    do {                                                              \
        __threadfence();                                              \
        __syncthreads();                                              \
        if (tid == 0) {                                               \
            atomicAdd((unsigned int*)barp, 1u);                       \
            while (*barp < target) { }                                \
            __threadfence();                                          \
        }                                                             \
        __syncthreads();                                              \
        target += NRG;                                                \
    } while (0)

    GROUP_SYNC();   // W slice + h0 init visible inside the group

    for (int t = 0; t < Tdim; t++) {
        const float* hc = g_hT[t & 1];
        float*       hn = g_hT[(t + 1) & 1];

        // Stage this step's 16 x values into smem.
        if (tid < BC)
            sX[tid] = __ldcg(&x[(cBase + tid) * Tdim + t]);

        // Load the group's hT block: 16 rows x 512 floats, coalesced LDG.128
        // + aligned STS.128.
        for (int i = tid; i < BC * (Hdim / 4); i += TPB) {
            int cc = i >> 7;          // Hdim/4 == 128
            int k4 = i & 127;
            float4 v = __ldcg(reinterpret_cast<const float4*>(hc + (cBase + cc) * Hdim) + k4);
            *reinterpret_cast<float4*>(sH + cc * PH + (k4 << 2)) = v;
        }
        __syncthreads();

        // ---- Compute: per lane 8 rows x 4 cols over a 64-wide k slice ----
        unsigned long long acc[8][4];
#pragma unroll
        for (int i = 0; i < 8; i++)
#pragma unroll
            for (int j = 0; j < 4; j++) acc[i][j] = 0ull;

#pragma unroll 2
        for (int k4 = 0; k4 < 16; k4++) {
            longlong2 lw[8];
            longlong2 lh[4];
#pragma unroll
            for (int i = 0; i < 8; i++)
                lw[i] = *reinterpret_cast<const longlong2*>(wbase + i * 8 * PW + (k4 << 2));
#pragma unroll
            for (int j = 0; j < 4; j++)
                lh[j] = *reinterpret_cast<const longlong2*>(hbase + j * 4 * PH + (k4 << 2));
#pragma unroll
            for (int i = 0; i < 8; i++)
#pragma unroll
                for (int j = 0; j < 4; j++) {
                    fma2(acc[i][j], (unsigned long long)lw[i].x, (unsigned long long)lh[j].x);
                    fma2(acc[i][j], (unsigned long long)lw[i].y, (unsigned long long)lh[j].y);
                }
        }

        // ---- Fold f32x2 pairs and store partials (conflict-free STS.32) ----
#pragma unroll
        for (int i = 0; i < 8; i++)
#pragma unroll
            for (int j = 0; j < 4; j++) {
                float2 a = *reinterpret_cast<float2*>(&acc[i][j]);
                myslab[i * 4 + j] = a.x + a.y;
            }
        __syncthreads();

        // ---- Reduce 8 k-partials, add input/bias, tanh, store h ----
        // Thread tid: outputs (rr, 4*cq+m), m=0..3. Conflict-free LDS.32.
#pragma unroll
        for (int m = 0; m < 4; m++) {
            const float* p = rdslab + m * SLAB_PITCH;
            float s = p[0];
#pragma unroll
            for (int w = 1; w < 8; w++) s += p[w * SLAB_WSTRIDE];
            int c = 4 * cq + m;
            float val = tanhf(s + whx_r * sX[c] + bh_r);
            __stcg(&hn[(cBase + c) * Hdim + rBase + rr], val);
        }

        GROUP_SYNC();   // release h stores to group peers; guards sH/sP reuse
    }

    // ---- Final projection (group-local batch columns).
    // T even -> h_last lives in g_hT[0], layout [B][H] (contiguous dot).
    if (tid < 20) {
        const int o  = rg * 20 + tid;            // 0..159 within group
        const int b  = cBase + o / NCLS;
        const int n  = o % NCLS;
        const float* wr = W_ph + n * Hdim;
        const float* hf = g_hT[0] + b * Hdim;
        float s = b_p[n];
#pragma unroll 4
        for (int k4 = 0; k4 < Hdim / 4; k4++) {
            float4 w = reinterpret_cast<const float4*>(wr)[k4];
            float4 h = __ldcg(reinterpret_cast<const float4*>(hf) + k4);
            s += w.x * h.x + w.y * h.y + w.z * h.z + w.w * h.w;
        }
        out[b * NCLS + n] = s;
    }
#undef GROUP_SYNC
}

extern "C" void kernel_launch(void* const* d_in, const int* in_sizes, int n_in,
                              void* d_out, int out_size) {
    const float* x      = (const float*)d_in[0];
    const float* h_init = (const float*)d_in[1];
    const float* W_hx   = (const float*)d_in[2];
    const float* W_hh   = (const float*)d_in[3];
    const float* b_h    = (const float*)d_in[4];
    const float* W_ph   = (const float*)d_in[5];
    const float* b_p    = (const float*)d_in[6];
    float* out = (float*)d_out;

    cudaFuncSetAttribute(rnn_persistent,
                         cudaFuncAttributeMaxDynamicSharedMemorySize, SMEM_BYTES);

    // Reset the barrier counters every launch (graph-capturable, no allocs).
    void* barp = nullptr;
    cudaGetSymbolAddress(&barp, g_bar);
    cudaMemsetAsync(barp, 0, NCG * 32 * sizeof(unsigned int), 0);

    rnn_persistent<<<NCTA, TPB, SMEM_BYTES, 0>>>(x, h_init, W_hx, W_hh,
                                                 b_h, W_ph, b_p, out);
}